// round 3
// baseline (speedup 1.0000x reference)
#include <cuda_runtime.h>
#include <math.h>

#define NTRK 4096
#define NVID 512

// ------------------------- device scratch (no runtime allocation) -------------------------
__device__ float    g_P[NTRK * 34 * 51 + 64];   // time-padded poses (n, 34, 51)
__device__ float    g_W1[160 * 128];            // conv1 weights [k*51+ci (pad->160)][co]
__device__ float    g_W2[384 * 128];            // conv2 weights [k*128+ci][co]
__device__ float    g_Wih[128 * 384];           // gru_wih^T [k][3H]
__device__ float    g_Whh[128 * 384];           // gru_whh^T [k][3H]
__device__ float    g_bgi[384];                 // bih + bhh(r,z only)
__device__ float    g_Whand[1024 * 128];        // folded img_w @ hand_w
__device__ float    g_bhand[128];               // folded img_b @ hand_w + hand_b
__device__ float    g_X1[NTRK * 34 * 128];      // conv1 out, time-padded
__device__ float    g_X2[NTRK * 32 * 128];      // conv2 out
__device__ float    g_GI[NTRK * 32 * 384];      // precomputed GRU input gates
__device__ float    g_H[NTRK * 128];            // GRU hidden
__device__ float    g_track[NTRK * 256];        // [kp_feat | hand_feat]
__device__ float    g_H1[NTRK * 256];           // fc1 out
__device__ unsigned g_vmax[NVID];               // ordered-encoded segment max

// ------------------------- helpers -------------------------
__device__ __forceinline__ float tf32r(float x) { asm("cvt.rna.tf32.f32 %0, %0;" : "+f"(x)); return x; }
__device__ __forceinline__ unsigned f2ord(float f) {
    unsigned u = __float_as_uint(f);
    return (u & 0x80000000u) ? ~u : (u | 0x80000000u);
}
__device__ __forceinline__ float ord2f(unsigned u) {
    return __uint_as_float((u & 0x80000000u) ? (u & 0x7fffffffu) : ~u);
}
__device__ __forceinline__ unsigned su32(const void* p) {
    unsigned r;
    asm("{.reg .u64 t; cvta.to.shared.u64 t, %1; cvt.u32.u64 %0, t;}" : "=r"(r) : "l"(p));
    return r;
}
__device__ __forceinline__ void cpa16(unsigned d, const void* s) {
    asm volatile("cp.async.cg.shared.global [%0],[%1],16;" :: "r"(d), "l"(s));
}
__device__ __forceinline__ void cpa4(unsigned d, const void* s) {
    asm volatile("cp.async.ca.shared.global [%0],[%1],4;" :: "r"(d), "l"(s));
}
__device__ __forceinline__ void cpcommit() { asm volatile("cp.async.commit_group;"); }
__device__ __forceinline__ void cpwait0() { asm volatile("cp.async.wait_group 0;"); }
__device__ __forceinline__ void cpwait1() { asm volatile("cp.async.wait_group 1;"); }
__device__ __forceinline__ void mma8(float* d, const unsigned* a, const unsigned* b) {
    asm volatile(
        "mma.sync.aligned.m16n8k8.row.col.f32.tf32.tf32.f32 "
        "{%0,%1,%2,%3},{%4,%5,%6,%7},{%8,%9},{%0,%1,%2,%3};"
        : "+f"(d[0]), "+f"(d[1]), "+f"(d[2]), "+f"(d[3])
        : "r"(a[0]), "r"(a[1]), "r"(a[2]), "r"(a[3]), "r"(b[0]), "r"(b[1]));
}
__device__ __forceinline__ float sigm(float x) { return 1.f / (1.f + __expf(-x)); }

// ------------------------- prep: layout/pad inputs, rearrange weights -------------------------
__global__ void prep1(const float* __restrict__ poses,
                      const float* __restrict__ c1w, const float* __restrict__ c2w,
                      const float* __restrict__ wih, const float* __restrict__ whh,
                      const float* __restrict__ bih, const float* __restrict__ bhh) {
    const long NP = (long)NTRK * 34 * 51;
    const long NX = (long)NTRK * 2 * 128;
    const long NH = (long)NTRK * 128;
    const long total = NP + NX + 20480 + 49152 + 49152 + 49152 + 384 + NH + NVID;
    for (long i = (long)blockIdx.x * blockDim.x + threadIdx.x; i < total;
         i += (long)gridDim.x * blockDim.x) {
        long idx = i;
        if (idx < NP) {  // padded poses (n, 34, 51); rows tp=0,33 zero
            long n = idx / (34 * 51);
            int r = (int)(idx % (34 * 51));
            int tp = r / 51, ci = r % 51;
            g_P[idx] = (tp == 0 || tp == 33) ? 0.f : poses[(n * 32 + (tp - 1)) * 51 + ci];
            continue;
        }
        idx -= NP;
        if (idx < NX) {  // zero X1 pad rows tp=0,33
            long n = idx >> 8;
            int r = (int)(idx & 255);
            int tp = (r < 128) ? 0 : 33;
            g_X1[n * 34 * 128 + tp * 128 + (r & 127)] = 0.f;
            continue;
        }
        idx -= NX;
        if (idx < 20480) {  // W1 [kk][co], kk = ktap*51+ci, pad 153..159 zero
            int kk = (int)(idx >> 7), co = (int)(idx & 127);
            float v = 0.f;
            if (kk < 153) { int kt = kk / 51, ci = kk % 51; v = tf32r(c1w[co * 153 + ci * 3 + kt]); }
            g_W1[idx] = v;
            continue;
        }
        idx -= 20480;
        if (idx < 49152) {  // W2 [kk][co], kk = ktap*128+ci
            int kk = (int)(idx >> 7), co = (int)(idx & 127);
            int kt = kk >> 7, ci = kk & 127;
            g_W2[idx] = tf32r(c2w[co * 384 + ci * 3 + kt]);
            continue;
        }
        idx -= 49152;
        if (idx < 49152) {  // Wih^T [k][j]
            int k = (int)(idx / 384), j = (int)(idx % 384);
            g_Wih[idx] = tf32r(wih[j * 128 + k]);
            continue;
        }
        idx -= 49152;
        if (idx < 49152) {  // Whh^T [k][j]
            int k = (int)(idx / 384), j = (int)(idx % 384);
            g_Whh[idx] = tf32r(whh[j * 128 + k]);
            continue;
        }
        idx -= 49152;
        if (idx < 384) { g_bgi[idx] = bih[idx] + ((idx < 256) ? bhh[idx] : 0.f); continue; }
        idx -= 384;
        if (idx < NH) { g_H[idx] = 0.f; continue; }
        idx -= NH;
        g_vmax[idx] = 0u;  // ord(-inf) < ord(any finite)
    }
}

// fold img_w @ hand_w (exact fp32) -> g_Whand; img_b @ hand_w + hand_b -> g_bhand
__global__ void foldw(const float* __restrict__ img_w, const float* __restrict__ img_b,
                      const float* __restrict__ hand_w, const float* __restrict__ hand_b) {
    __shared__ float sv[512];
    int b = blockIdx.x, c = threadIdx.x;
    if (b < 1024) {
        for (int q = c; q < 512; q += 128) sv[q] = img_w[b * 512 + q];
        __syncthreads();
        float a = 0.f;
#pragma unroll 8
        for (int q = 0; q < 512; q++) a += sv[q] * hand_w[q * 128 + c];
        g_Whand[b * 128 + c] = tf32r(a);
    } else {
        for (int q = c; q < 512; q += 128) sv[q] = img_b[q];
        __syncthreads();
        float a = hand_b[c];
        for (int q = 0; q < 512; q++) a += sv[q] * hand_w[q * 128 + c];
        g_bhand[c] = a;
    }
}

// ------------------------- generic tf32 GEMM -------------------------
// MODE 0: C = [relu](A@B + bias), group-addressed rows in/out
// MODE 1: hand GEMM, epilogue = per-track max over 64 rows -> g_track[:,128:]
// MODE 2: GRU step,  epilogue = gate math, in-place h update
template <int BM, int BN, int WM, int WN, int VEC, int ARPG, int ORPG, int MODE, bool RELU>
__global__ void __launch_bounds__(256) gemm_k(
    const float* __restrict__ A, long aGS, long aRS, long aOfs,
    const float* __restrict__ Bm, int ldb,
    const float* __restrict__ bias,
    float* __restrict__ Cout, long oGS, long oRS, long oOfs,
    int K,
    const float* __restrict__ gi, const float* __restrict__ bhhn, int step) {
    constexpr int BK = 32;
    constexpr int WARPS_M = BM / WM, WARPS_N = BN / WN;
    static_assert(WARPS_M * WARPS_N == 8, "8 warps");
    constexpr int FM = WM / 16, FN = WN / 8;
    constexpr int SAST = BK + 4;   // 36 floats: conflict-free, 16B-aligned rows
    constexpr int SBST = BN + 8;   // conflict-free, 16B-aligned rows
    constexpr int ASZ = BM * SAST, BSZ = BK * SBST;
    extern __shared__ float sm[];
    float* sA = sm;
    float* sB = sm + 2 * ASZ;

    const int tid = threadIdx.x, lane = tid & 31, wid = tid >> 5;
    const int wm = wid % WARPS_M, wn = wid / WARPS_M;
    const int m0 = blockIdx.x * BM, n0 = blockIdx.y * BN;

    float acc[FM][FN][4];
#pragma unroll
    for (int i = 0; i < FM; i++)
#pragma unroll
        for (int j = 0; j < FN; j++)
#pragma unroll
            for (int q = 0; q < 4; q++) acc[i][j][q] = 0.f;

    constexpr int A_LOADS = BM * BK / (256 * VEC);
    const float* aP[A_LOADS];
    unsigned aD[A_LOADS];
#pragma unroll
    for (int i = 0; i < A_LOADS; i++) {
        int ch = tid + i * 256;
        int row, cx;
        if (VEC == 4) { row = ch >> 3; cx = (ch & 7) * 4; }
        else          { row = ch >> 5; cx = ch & 31; }
        int gr = m0 + row;
        const float* rp = ARPG ? (A + (long)(gr / ARPG) * aGS + (long)(gr % ARPG) * aRS + aOfs)
                               : (A + (long)gr * aRS + aOfs);
        aP[i] = rp + cx;
        aD[i] = su32(sA) + (unsigned)((row * SAST + cx) * 4);
    }
    constexpr int B_LOADS = BK * BN / 1024;
    const float* bP[B_LOADS];
    unsigned bD[B_LOADS];
#pragma unroll
    for (int i = 0; i < B_LOADS; i++) {
        int ch = tid + i * 256;
        int row = ch / (BN / 4);
        int cx = (ch % (BN / 4)) * 4;
        bP[i] = Bm + (long)row * ldb + n0 + cx;
        bD[i] = su32(sB) + (unsigned)((row * SBST + cx) * 4);
    }

    auto load = [&](int buf, int k0) {
#pragma unroll
        for (int i = 0; i < A_LOADS; i++) {
            if (VEC == 4) cpa16(aD[i] + buf * ASZ * 4, aP[i] + k0);
            else          cpa4(aD[i] + buf * ASZ * 4, aP[i] + k0);
        }
#pragma unroll
        for (int i = 0; i < B_LOADS; i++) cpa16(bD[i] + buf * BSZ * 4, bP[i] + (long)k0 * ldb);
        cpcommit();
    };

    const int NS = K / BK;
    load(0, 0);
    for (int s = 0; s < NS; s++) {
        if (s + 1 < NS) { load((s + 1) & 1, (s + 1) * BK); cpwait1(); }
        else cpwait0();
        __syncthreads();
        const float* cA = sA + (s & 1) * ASZ;
        const float* cB = sB + (s & 1) * BSZ;
#pragma unroll
        for (int kk = 0; kk < BK; kk += 8) {
            unsigned af[FM][4], bf[FN][2];
            const int ar0 = wm * WM + (lane >> 2), ac = kk + (lane & 3);
#pragma unroll
            for (int i = 0; i < FM; i++) {
                int r = ar0 + i * 16;
                af[i][0] = __float_as_uint(cA[(r) * SAST + ac]);
                af[i][1] = __float_as_uint(cA[(r + 8) * SAST + ac]);
                af[i][2] = __float_as_uint(cA[(r) * SAST + ac + 4]);
                af[i][3] = __float_as_uint(cA[(r + 8) * SAST + ac + 4]);
            }
            const int bc0 = wn * WN + (lane >> 2), br = kk + (lane & 3);
#pragma unroll
            for (int j = 0; j < FN; j++) {
                bf[j][0] = __float_as_uint(cB[(br) * SBST + bc0 + j * 8]);
                bf[j][1] = __float_as_uint(cB[(br + 4) * SBST + bc0 + j * 8]);
            }
#pragma unroll
            for (int i = 0; i < FM; i++)
#pragma unroll
                for (int j = 0; j < FN; j++) mma8(acc[i][j], af[i], bf[j]);
        }
        __syncthreads();
    }

    // ------------------------- epilogue -------------------------
    if (MODE == 0) {
#pragma unroll
        for (int i = 0; i < FM; i++) {
            int lr = wm * WM + i * 16 + (lane >> 2);
#pragma unroll
            for (int j = 0; j < FN; j++) {
                int col = n0 + wn * WN + j * 8 + (lane & 3) * 2;
                float b0 = bias ? bias[col] : 0.f;
                float b1 = bias ? bias[col + 1] : 0.f;
#pragma unroll
                for (int h = 0; h < 2; h++) {
                    int gr = m0 + lr + h * 8;
                    float v0 = acc[i][j][h * 2 + 0] + b0;
                    float v1 = acc[i][j][h * 2 + 1] + b1;
                    if (RELU) { v0 = fmaxf(v0, 0.f); v1 = fmaxf(v1, 0.f); }
                    float* op = ORPG ? (Cout + (long)(gr / ORPG) * oGS + (long)(gr % ORPG) * oRS + oOfs + col)
                                     : (Cout + (long)gr * oRS + oOfs + col);
                    ((float2*)op)[0] = make_float2(v0, v1);
                }
            }
        }
    } else if (MODE == 1) {  // hand: per-track max over 64 rows (2 tracks / block)
        __syncthreads();
        constexpr int CST = 132;
#pragma unroll
        for (int i = 0; i < FM; i++) {
            int lr = wm * WM + i * 16 + (lane >> 2);
#pragma unroll
            for (int j = 0; j < FN; j++) {
                int lc = wn * WN + j * 8 + (lane & 3) * 2;
                ((float2*)&sm[(lr) * CST + lc])[0] = make_float2(acc[i][j][0], acc[i][j][1]);
                ((float2*)&sm[(lr + 8) * CST + lc])[0] = make_float2(acc[i][j][2], acc[i][j][3]);
            }
        }
        __syncthreads();
        int trk = tid >> 7, c = tid & 127;
        float mx = -3.4e38f;
#pragma unroll 8
        for (int r = 0; r < 64; r++) mx = fmaxf(mx, sm[(trk * 64 + r) * CST + c]);
        mx += bias[c];
        int track = (m0 >> 6) + trk;
        Cout[(long)track * 256 + 128 + c] = mx;
    } else {  // MODE 2: GRU step (BM=32, BN=384, FM=1)
        __syncthreads();
        constexpr int CST = 392;
        {
            int lr = wm * WM + (lane >> 2);
#pragma unroll
            for (int j = 0; j < FN; j++) {
                int lc = wn * WN + j * 8 + (lane & 3) * 2;
                ((float2*)&sm[(lr) * CST + lc])[0] = make_float2(acc[0][j][0], acc[0][j][1]);
                ((float2*)&sm[(lr + 8) * CST + lc])[0] = make_float2(acc[0][j][2], acc[0][j][3]);
            }
        }
        __syncthreads();
#pragma unroll
        for (int it = 0; it < 16; it++) {
            int idx = tid + it * 256;  // 32 rows x 128 cols
            int c = idx & 127, row = idx >> 7;
            int trk = m0 + row;
            const float* gp = gi + ((long)trk * 32 + step) * 384;
            float rr = sigm(gp[c] + sm[row * CST + c]);
            float zz = sigm(gp[128 + c] + sm[row * CST + 128 + c]);
            float nn = tanhf(gp[256 + c] + rr * (sm[row * CST + 256 + c] + bhhn[c]));
            float ho = Cout[(long)trk * 128 + c];
            Cout[(long)trk * 128 + c] = (1.f - zz) * nn + zz * ho;
        }
    }
}

// ------------------------- small kernels -------------------------
__global__ void copyH() {
    int i = blockIdx.x * 256 + threadIdx.x;  // 524288
    int m = i >> 7, c = i & 127;
    g_track[(long)m * 256 + c] = g_H[i];
}

__global__ void fc2seg(const float* __restrict__ w, const float* __restrict__ b2,
                       const int* __restrict__ vidx) {
    __shared__ float sw[256];
    int t = threadIdx.x;
    sw[t] = w[t];
    __syncthreads();
    int m = blockIdx.x * 256 + t;
    const float* h = &g_H1[(long)m * 256];
    float a = b2[0];
#pragma unroll 16
    for (int q = 0; q < 256; q++) a += h[q] * sw[q];
    atomicMax(&g_vmax[vidx[m]], f2ord(a));
}

__global__ void finalk(const float* __restrict__ nts, float* __restrict__ out) {
    int v = blockIdx.x * 256 + threadIdx.x;
    if (v < NVID) {
        unsigned u = g_vmax[v];
        float lg = (u == 0u) ? nts[0] : ord2f(u);
        out[v] = 1.f / (1.f + expf(-lg));
    }
}

// ------------------------- launch -------------------------
extern "C" void kernel_launch(void* const* d_in, const int* in_sizes, int n_in,
                              void* d_out, int out_size) {
    const float* poses  = (const float*)d_in[0];
    const float* hands  = (const float*)d_in[1];
    const int*   vidx   = (const int*)d_in[2];
    const float* c1w    = (const float*)d_in[3];
    const float* c1b    = (const float*)d_in[4];
    const float* c2w    = (const float*)d_in[5];
    const float* c2b    = (const float*)d_in[6];
    const float* wih    = (const float*)d_in[7];
    const float* whh    = (const float*)d_in[8];
    const float* bih    = (const float*)d_in[9];
    const float* bhh    = (const float*)d_in[10];
    const float* img_w  = (const float*)d_in[11];
    const float* img_b  = (const float*)d_in[12];
    const float* hand_w = (const float*)d_in[13];
    const float* hand_b = (const float*)d_in[14];
    const float* fc1w   = (const float*)d_in[15];
    const float* fc1b   = (const float*)d_in[16];
    const float* fc2w   = (const float*)d_in[17];
    const float* fc2b   = (const float*)d_in[18];
    const float* nts    = (const float*)d_in[19];
    float* out = (float*)d_out;

    float *pP, *pW1, *pW2, *pWih, *pWhh, *pbgi, *pWhand, *pbhand, *pX1, *pX2, *pGI, *pH, *pTrack, *pH1;
    cudaGetSymbolAddress((void**)&pP, g_P);
    cudaGetSymbolAddress((void**)&pW1, g_W1);
    cudaGetSymbolAddress((void**)&pW2, g_W2);
    cudaGetSymbolAddress((void**)&pWih, g_Wih);
    cudaGetSymbolAddress((void**)&pWhh, g_Whh);
    cudaGetSymbolAddress((void**)&pbgi, g_bgi);
    cudaGetSymbolAddress((void**)&pWhand, g_Whand);
    cudaGetSymbolAddress((void**)&pbhand, g_bhand);
    cudaGetSymbolAddress((void**)&pX1, g_X1);
    cudaGetSymbolAddress((void**)&pX2, g_X2);
    cudaGetSymbolAddress((void**)&pGI, g_GI);
    cudaGetSymbolAddress((void**)&pH, g_H);
    cudaGetSymbolAddress((void**)&pTrack, g_track);
    cudaGetSymbolAddress((void**)&pH1, g_H1);

    constexpr int SM_STD = (2 * 128 * 36 + 2 * 32 * 136) * 4;  // 71680 B
    constexpr int SM_GRU = (2 * 32 * 36 + 2 * 32 * 392) * 4;   // 109568 B

    auto* kConv1 = gemm_k<128, 128, 32, 64, 1, 32, 32, 0, true>;
    auto* kConv2 = gemm_k<128, 128, 32, 64, 4, 32, 0, 0, true>;
    auto* kGi    = gemm_k<128, 128, 32, 64, 4, 0, 0, 0, false>;
    auto* kGru   = gemm_k<32, 384, 16, 96, 4, 0, 0, 2, false>;
    auto* kHand  = gemm_k<128, 128, 32, 64, 4, 0, 0, 1, false>;
    auto* kFc1   = gemm_k<128, 128, 32, 64, 4, 0, 0, 0, true>;

    cudaFuncSetAttribute(kConv1, cudaFuncAttributeMaxDynamicSharedMemorySize, SM_STD);
    cudaFuncSetAttribute(kConv2, cudaFuncAttributeMaxDynamicSharedMemorySize, SM_STD);
    cudaFuncSetAttribute(kGi, cudaFuncAttributeMaxDynamicSharedMemorySize, SM_STD);
    cudaFuncSetAttribute(kGru, cudaFuncAttributeMaxDynamicSharedMemorySize, SM_GRU);
    cudaFuncSetAttribute(kHand, cudaFuncAttributeMaxDynamicSharedMemorySize, SM_STD);
    cudaFuncSetAttribute(kFc1, cudaFuncAttributeMaxDynamicSharedMemorySize, SM_STD);

    prep1<<<4096, 256>>>(poses, c1w, c2w, wih, whh, bih, bhh);
    foldw<<<1025, 128>>>(img_w, img_b, hand_w, hand_b);

    // conv1: im2col rows are contiguous slices of padded g_P (stride 51 -> VEC=1)
    kConv1<<<dim3(1024, 1), 256, SM_STD>>>(pP, 34 * 51, 51, 0, pW1, 128, c1b,
                                           pX1, 34 * 128, 128, 128, 160, nullptr, nullptr, 0);
    // conv2: contiguous im2col over time-padded X1
    kConv2<<<dim3(1024, 1), 256, SM_STD>>>(pX1, 34 * 128, 128, 0, pW2, 128, c2b,
                                           pX2, 0, 128, 0, 384, nullptr, nullptr, 0);
    // GRU input gates, biases folded
    kGi<<<dim3(1024, 3), 256, SM_STD>>>(pX2, 0, 128, 0, pWih, 384, pbgi,
                                        pGI, 0, 384, 0, 128, nullptr, nullptr, 0);
    // GRU recurrence: 32 in-place steps
    for (int t = 0; t < 32; t++)
        kGru<<<dim3(128, 1), 256, SM_GRU>>>(pH, 0, 128, 0, pWhh, 384, nullptr,
                                            pH, 0, 128, 0, 128, pGI, bhh + 256, t);
    // hand path with fused max epilogue
    kHand<<<dim3(2048, 1), 256, SM_STD>>>(hands, 0, 1024, 0, pWhand, 128, pbhand,
                                          pTrack, 0, 0, 0, 1024, nullptr, nullptr, 0);
    copyH<<<2048, 256>>>();
    // fc1
    kFc1<<<dim3(32, 2), 256, SM_STD>>>(pTrack, 0, 256, 0, fc1w, 256, fc1b,
                                       pH1, 0, 256, 0, 256, nullptr, nullptr, 0);
    // fc2 + segmented max + sigmoid
    fc2seg<<<16, 256>>>(fc2w, fc2b, vidx);
    finalk<<<2, 256>>>(nts, out);
}

// round 4
// speedup vs baseline: 1.4060x; 1.4060x over previous
#include <cuda_runtime.h>
#include <math.h>

#define NTRK 4096
#define NVID 512

// ------------------------- device scratch (no runtime allocation) -------------------------
__device__ float    g_P[NTRK * 34 * 51 + 64];   // time-padded poses (n, 34, 51)
__device__ float    g_W1[160 * 128];            // conv1 weights [k*51+ci (pad->160)][co]
__device__ float    g_W2[384 * 128];            // conv2 weights [k*128+ci][co]
__device__ float    g_Wih[128 * 384];           // gru_wih^T [k][3H]
__device__ float    g_Whh[128 * 384];           // gru_whh^T [k][3H]
__device__ float    g_bgi[384];                 // bih + bhh(r,z only)
__device__ float    g_Whand[1024 * 128];        // folded img_w @ hand_w
__device__ float    g_bhand[128];               // folded img_b @ hand_w + hand_b
__device__ float    g_X1[NTRK * 34 * 128];      // conv1 out, time-padded
__device__ float    g_X2[NTRK * 32 * 128];      // conv2 out
__device__ float    g_GI[NTRK * 32 * 384];      // precomputed GRU input gates
__device__ float    g_H[NTRK * 128];            // GRU hidden
__device__ float    g_track[NTRK * 256];        // [kp_feat | hand_feat]
__device__ float    g_H1[NTRK * 256];           // fc1 out
__device__ unsigned g_vmax[NVID];               // ordered-encoded segment max

// ------------------------- helpers -------------------------
__device__ __forceinline__ float tf32r(float x) { asm("cvt.rna.tf32.f32 %0, %0;" : "+f"(x)); return x; }
__device__ __forceinline__ unsigned f2ord(float f) {
    unsigned u = __float_as_uint(f);
    return (u & 0x80000000u) ? ~u : (u | 0x80000000u);
}
__device__ __forceinline__ float ord2f(unsigned u) {
    return __uint_as_float((u & 0x80000000u) ? (u & 0x7fffffffu) : ~u);
}
__device__ __forceinline__ unsigned su32(const void* p) {
    unsigned r;
    asm("{.reg .u64 t; cvta.to.shared.u64 t, %1; cvt.u32.u64 %0, t;}" : "=r"(r) : "l"(p));
    return r;
}
__device__ __forceinline__ void cpa16(unsigned d, const void* s) {
    asm volatile("cp.async.cg.shared.global [%0],[%1],16;" :: "r"(d), "l"(s));
}
__device__ __forceinline__ void cpa4(unsigned d, const void* s) {
    asm volatile("cp.async.ca.shared.global [%0],[%1],4;" :: "r"(d), "l"(s));
}
__device__ __forceinline__ void cpcommit() { asm volatile("cp.async.commit_group;"); }
__device__ __forceinline__ void cpwait0() { asm volatile("cp.async.wait_group 0;"); }
__device__ __forceinline__ void cpwait1() { asm volatile("cp.async.wait_group 1;"); }
__device__ __forceinline__ void mma8(float* d, const unsigned* a, const unsigned* b) {
    asm volatile(
        "mma.sync.aligned.m16n8k8.row.col.f32.tf32.tf32.f32 "
        "{%0,%1,%2,%3},{%4,%5,%6,%7},{%8,%9},{%0,%1,%2,%3};"
        : "+f"(d[0]), "+f"(d[1]), "+f"(d[2]), "+f"(d[3])
        : "r"(a[0]), "r"(a[1]), "r"(a[2]), "r"(a[3]), "r"(b[0]), "r"(b[1]));
}
__device__ __forceinline__ float sigm(float x) { return 1.f / (1.f + __expf(-x)); }

// ------------------------- prep: layout/pad inputs, rearrange weights -------------------------
__global__ void prep1(const float* __restrict__ poses,
                      const float* __restrict__ c1w, const float* __restrict__ c2w,
                      const float* __restrict__ wih, const float* __restrict__ whh,
                      const float* __restrict__ bih, const float* __restrict__ bhh) {
    const long NP = (long)NTRK * 34 * 51;
    const long NX = (long)NTRK * 2 * 128;
    const long NH = (long)NTRK * 128;
    const long total = NP + NX + 20480 + 49152 + 49152 + 49152 + 384 + NH + NVID;
    for (long i = (long)blockIdx.x * blockDim.x + threadIdx.x; i < total;
         i += (long)gridDim.x * blockDim.x) {
        long idx = i;
        if (idx < NP) {  // padded poses (n, 34, 51); rows tp=0,33 zero
            long n = idx / (34 * 51);
            int r = (int)(idx % (34 * 51));
            int tp = r / 51, ci = r % 51;
            g_P[idx] = (tp == 0 || tp == 33) ? 0.f : poses[(n * 32 + (tp - 1)) * 51 + ci];
            continue;
        }
        idx -= NP;
        if (idx < NX) {  // zero X1 pad rows tp=0,33
            long n = idx >> 8;
            int r = (int)(idx & 255);
            int tp = (r < 128) ? 0 : 33;
            g_X1[n * 34 * 128 + tp * 128 + (r & 127)] = 0.f;
            continue;
        }
        idx -= NX;
        if (idx < 20480) {  // W1 [kk][co], kk = ktap*51+ci, pad 153..159 zero
            int kk = (int)(idx >> 7), co = (int)(idx & 127);
            float v = 0.f;
            if (kk < 153) { int kt = kk / 51, ci = kk % 51; v = tf32r(c1w[co * 153 + ci * 3 + kt]); }
            g_W1[idx] = v;
            continue;
        }
        idx -= 20480;
        if (idx < 49152) {  // W2 [kk][co], kk = ktap*128+ci
            int kk = (int)(idx >> 7), co = (int)(idx & 127);
            int kt = kk >> 7, ci = kk & 127;
            g_W2[idx] = tf32r(c2w[co * 384 + ci * 3 + kt]);
            continue;
        }
        idx -= 49152;
        if (idx < 49152) {  // Wih^T [k][j]
            int k = (int)(idx / 384), j = (int)(idx % 384);
            g_Wih[idx] = tf32r(wih[j * 128 + k]);
            continue;
        }
        idx -= 49152;
        if (idx < 49152) {  // Whh^T [k][j]
            int k = (int)(idx / 384), j = (int)(idx % 384);
            g_Whh[idx] = tf32r(whh[j * 128 + k]);
            continue;
        }
        idx -= 49152;
        if (idx < 384) { g_bgi[idx] = bih[idx] + ((idx < 256) ? bhh[idx] : 0.f); continue; }
        idx -= 384;
        if (idx < NH) { g_H[idx] = 0.f; continue; }
        idx -= NH;
        g_vmax[idx] = 0u;  // ord(-inf) < ord(any finite)
    }
}

// fold img_w @ hand_w (exact fp32) -> g_Whand; img_b @ hand_w + hand_b -> g_bhand
__global__ void foldw(const float* __restrict__ img_w, const float* __restrict__ img_b,
                      const float* __restrict__ hand_w, const float* __restrict__ hand_b) {
    __shared__ float sv[512];
    int b = blockIdx.x, c = threadIdx.x;
    if (b < 1024) {
        for (int q = c; q < 512; q += 128) sv[q] = img_w[b * 512 + q];
        __syncthreads();
        float a = 0.f;
#pragma unroll 8
        for (int q = 0; q < 512; q++) a += sv[q] * hand_w[q * 128 + c];
        g_Whand[b * 128 + c] = tf32r(a);
    } else {
        for (int q = c; q < 512; q += 128) sv[q] = img_b[q];
        __syncthreads();
        float a = hand_b[c];
        for (int q = 0; q < 512; q++) a += sv[q] * hand_w[q * 128 + c];
        g_bhand[c] = a;
    }
}

// ------------------------- generic tf32 GEMM -------------------------
// MODE 0: C = [relu](A@B + bias), group-addressed rows in/out
// MODE 1: hand GEMM, epilogue = per-track max over 64 rows -> g_track[:,128:]
// MODE 2: GRU step,  epilogue = gate math, in-place h update
template <int BM, int BN, int WM, int WN, int VEC, int ARPG, int ORPG, int MODE, bool RELU>
__global__ void __launch_bounds__(256) gemm_k(
    const float* __restrict__ A, long aGS, long aRS, long aOfs,
    const float* __restrict__ Bm, int ldb,
    const float* __restrict__ bias,
    float* __restrict__ Cout, long oGS, long oRS, long oOfs,
    int K,
    const float* __restrict__ gi, const float* __restrict__ bhhn, int step) {
    constexpr int BK = 32;
    constexpr int WARPS_M = BM / WM, WARPS_N = BN / WN;
    static_assert(WARPS_M * WARPS_N == 8, "8 warps");
    constexpr int FM = WM / 16, FN = WN / 8;
    constexpr int SAST = BK + 4;   // 36 floats: conflict-free, 16B-aligned rows
    constexpr int SBST = BN + 8;   // conflict-free, 16B-aligned rows
    constexpr int ASZ = BM * SAST, BSZ = BK * SBST;
    extern __shared__ float sm[];
    float* sA = sm;
    float* sB = sm + 2 * ASZ;

    const int tid = threadIdx.x, lane = tid & 31, wid = tid >> 5;
    const int wm = wid % WARPS_M, wn = wid / WARPS_M;
    const int m0 = blockIdx.x * BM, n0 = blockIdx.y * BN;

    float acc[FM][FN][4];
#pragma unroll
    for (int i = 0; i < FM; i++)
#pragma unroll
        for (int j = 0; j < FN; j++)
#pragma unroll
            for (int q = 0; q < 4; q++) acc[i][j][q] = 0.f;

    constexpr int A_LOADS = BM * BK / (256 * VEC);
    const float* aP[A_LOADS];
    unsigned aD[A_LOADS];
#pragma unroll
    for (int i = 0; i < A_LOADS; i++) {
        int ch = tid + i * 256;
        int row, cx;
        if (VEC == 4) { row = ch >> 3; cx = (ch & 7) * 4; }
        else          { row = ch >> 5; cx = ch & 31; }
        int gr = m0 + row;
        const float* rp = ARPG ? (A + (long)(gr / ARPG) * aGS + (long)(gr % ARPG) * aRS + aOfs)
                               : (A + (long)gr * aRS + aOfs);
        aP[i] = rp + cx;
        aD[i] = su32(sA) + (unsigned)((row * SAST + cx) * 4);
    }
    constexpr int B_LOADS = BK * BN / 1024;
    const float* bP[B_LOADS];
    unsigned bD[B_LOADS];
#pragma unroll
    for (int i = 0; i < B_LOADS; i++) {
        int ch = tid + i * 256;
        int row = ch / (BN / 4);
        int cx = (ch % (BN / 4)) * 4;
        bP[i] = Bm + (long)row * ldb + n0 + cx;
        bD[i] = su32(sB) + (unsigned)((row * SBST + cx) * 4);
    }

    auto load = [&](int buf, int k0) {
#pragma unroll
        for (int i = 0; i < A_LOADS; i++) {
            if (VEC == 4) cpa16(aD[i] + buf * ASZ * 4, aP[i] + k0);
            else          cpa4(aD[i] + buf * ASZ * 4, aP[i] + k0);
        }
#pragma unroll
        for (int i = 0; i < B_LOADS; i++) cpa16(bD[i] + buf * BSZ * 4, bP[i] + (long)k0 * ldb);
        cpcommit();
    };

    const int NS = K / BK;
    load(0, 0);
    for (int s = 0; s < NS; s++) {
        if (s + 1 < NS) { load((s + 1) & 1, (s + 1) * BK); cpwait1(); }
        else cpwait0();
        __syncthreads();
        const float* cA = sA + (s & 1) * ASZ;
        const float* cB = sB + (s & 1) * BSZ;
#pragma unroll
        for (int kk = 0; kk < BK; kk += 8) {
            unsigned af[FM][4], bf[FN][2];
            const int ar0 = wm * WM + (lane >> 2), ac = kk + (lane & 3);
#pragma unroll
            for (int i = 0; i < FM; i++) {
                int r = ar0 + i * 16;
                af[i][0] = __float_as_uint(cA[(r) * SAST + ac]);
                af[i][1] = __float_as_uint(cA[(r + 8) * SAST + ac]);
                af[i][2] = __float_as_uint(cA[(r) * SAST + ac + 4]);
                af[i][3] = __float_as_uint(cA[(r + 8) * SAST + ac + 4]);
            }
            const int bc0 = wn * WN + (lane >> 2), br = kk + (lane & 3);
#pragma unroll
            for (int j = 0; j < FN; j++) {
                bf[j][0] = __float_as_uint(cB[(br) * SBST + bc0 + j * 8]);
                bf[j][1] = __float_as_uint(cB[(br + 4) * SBST + bc0 + j * 8]);
            }
#pragma unroll
            for (int i = 0; i < FM; i++)
#pragma unroll
                for (int j = 0; j < FN; j++) mma8(acc[i][j], af[i], bf[j]);
        }
        __syncthreads();
    }

    // ------------------------- epilogue -------------------------
    if (MODE == 0) {
#pragma unroll
        for (int i = 0; i < FM; i++) {
            int lr = wm * WM + i * 16 + (lane >> 2);
#pragma unroll
            for (int j = 0; j < FN; j++) {
                int col = n0 + wn * WN + j * 8 + (lane & 3) * 2;
                float b0 = bias ? bias[col] : 0.f;
                float b1 = bias ? bias[col + 1] : 0.f;
#pragma unroll
                for (int h = 0; h < 2; h++) {
                    int gr = m0 + lr + h * 8;
                    float v0 = acc[i][j][h * 2 + 0] + b0;
                    float v1 = acc[i][j][h * 2 + 1] + b1;
                    if (RELU) { v0 = fmaxf(v0, 0.f); v1 = fmaxf(v1, 0.f); }
                    float* op = ORPG ? (Cout + (long)(gr / ORPG) * oGS + (long)(gr % ORPG) * oRS + oOfs + col)
                                     : (Cout + (long)gr * oRS + oOfs + col);
                    ((float2*)op)[0] = make_float2(v0, v1);
                }
            }
        }
    } else if (MODE == 1) {  // hand: per-track max over 64 rows (2 tracks / block)
        __syncthreads();
        constexpr int CST = 132;
#pragma unroll
        for (int i = 0; i < FM; i++) {
            int lr = wm * WM + i * 16 + (lane >> 2);
#pragma unroll
            for (int j = 0; j < FN; j++) {
                int lc = wn * WN + j * 8 + (lane & 3) * 2;
                ((float2*)&sm[(lr) * CST + lc])[0] = make_float2(acc[i][j][0], acc[i][j][1]);
                ((float2*)&sm[(lr + 8) * CST + lc])[0] = make_float2(acc[i][j][2], acc[i][j][3]);
            }
        }
        __syncthreads();
        int trk = tid >> 7, c = tid & 127;
        float mx = -3.4e38f;
#pragma unroll 8
        for (int r = 0; r < 64; r++) mx = fmaxf(mx, sm[(trk * 64 + r) * CST + c]);
        mx += bias[c];
        int track = (m0 >> 6) + trk;
        Cout[(long)track * 256 + 128 + c] = mx;
    } else {  // MODE 2: GRU step (BM=32, BN=384, FM=1)
        __syncthreads();
        constexpr int CST = 392;
        {
            int lr = wm * WM + (lane >> 2);
#pragma unroll
            for (int j = 0; j < FN; j++) {
                int lc = wn * WN + j * 8 + (lane & 3) * 2;
                ((float2*)&sm[(lr) * CST + lc])[0] = make_float2(acc[0][j][0], acc[0][j][1]);
                ((float2*)&sm[(lr + 8) * CST + lc])[0] = make_float2(acc[0][j][2], acc[0][j][3]);
            }
        }
        __syncthreads();
#pragma unroll
        for (int it = 0; it < 16; it++) {
            int idx = tid + it * 256;  // 32 rows x 128 cols
            int c = idx & 127, row = idx >> 7;
            int trk = m0 + row;
            const float* gp = gi + ((long)trk * 32 + step) * 384;
            float rr = sigm(gp[c] + sm[row * CST + c]);
            float zz = sigm(gp[128 + c] + sm[row * CST + 128 + c]);
            float nn = tanhf(gp[256 + c] + rr * (sm[row * CST + 256 + c] + bhhn[c]));
            float ho = Cout[(long)trk * 128 + c];
            Cout[(long)trk * 128 + c] = (1.f - zz) * nn + zz * ho;
        }
    }
}

// ------------------------- small kernels -------------------------
__global__ void copyH() {
    int i = blockIdx.x * 256 + threadIdx.x;  // 524288
    int m = i >> 7, c = i & 127;
    g_track[(long)m * 256 + c] = g_H[i];
}

__global__ void fc2seg(const float* __restrict__ w, const float* __restrict__ b2,
                       const int* __restrict__ vidx) {
    __shared__ float sw[256];
    int t = threadIdx.x;
    sw[t] = w[t];
    __syncthreads();
    int m = blockIdx.x * 256 + t;
    const float* h = &g_H1[(long)m * 256];
    float a = b2[0];
#pragma unroll 16
    for (int q = 0; q < 256; q++) a += h[q] * sw[q];
    atomicMax(&g_vmax[vidx[m]], f2ord(a));
}

__global__ void finalk(const float* __restrict__ nts, float* __restrict__ out) {
    int v = blockIdx.x * 256 + threadIdx.x;
    if (v < NVID) {
        unsigned u = g_vmax[v];
        float lg = (u == 0u) ? nts[0] : ord2f(u);
        out[v] = 1.f / (1.f + expf(-lg));
    }
}

// ------------------------- launch -------------------------
extern "C" void kernel_launch(void* const* d_in, const int* in_sizes, int n_in,
                              void* d_out, int out_size) {
    const float* poses  = (const float*)d_in[0];
    const float* hands  = (const float*)d_in[1];
    const int*   vidx   = (const int*)d_in[2];
    const float* c1w    = (const float*)d_in[3];
    const float* c1b    = (const float*)d_in[4];
    const float* c2w    = (const float*)d_in[5];
    const float* c2b    = (const float*)d_in[6];
    const float* wih    = (const float*)d_in[7];
    const float* whh    = (const float*)d_in[8];
    const float* bih    = (const float*)d_in[9];
    const float* bhh    = (const float*)d_in[10];
    const float* img_w  = (const float*)d_in[11];
    const float* img_b  = (const float*)d_in[12];
    const float* hand_w = (const float*)d_in[13];
    const float* hand_b = (const float*)d_in[14];
    const float* fc1w   = (const float*)d_in[15];
    const float* fc1b   = (const float*)d_in[16];
    const float* fc2w   = (const float*)d_in[17];
    const float* fc2b   = (const float*)d_in[18];
    const float* nts    = (const float*)d_in[19];
    float* out = (float*)d_out;

    float *pP, *pW1, *pW2, *pWih, *pWhh, *pbgi, *pWhand, *pbhand, *pX1, *pX2, *pGI, *pH, *pTrack, *pH1;
    cudaGetSymbolAddress((void**)&pP, g_P);
    cudaGetSymbolAddress((void**)&pW1, g_W1);
    cudaGetSymbolAddress((void**)&pW2, g_W2);
    cudaGetSymbolAddress((void**)&pWih, g_Wih);
    cudaGetSymbolAddress((void**)&pWhh, g_Whh);
    cudaGetSymbolAddress((void**)&pbgi, g_bgi);
    cudaGetSymbolAddress((void**)&pWhand, g_Whand);
    cudaGetSymbolAddress((void**)&pbhand, g_bhand);
    cudaGetSymbolAddress((void**)&pX1, g_X1);
    cudaGetSymbolAddress((void**)&pX2, g_X2);
    cudaGetSymbolAddress((void**)&pGI, g_GI);
    cudaGetSymbolAddress((void**)&pH, g_H);
    cudaGetSymbolAddress((void**)&pTrack, g_track);
    cudaGetSymbolAddress((void**)&pH1, g_H1);

    constexpr int SM_STD = (2 * 128 * 36 + 2 * 32 * 136) * 4;  // 71680 B
    constexpr int SM_GRU = (2 * 32 * 36 + 2 * 32 * 392) * 4;   // 109568 B

    auto* kConv1 = gemm_k<128, 128, 32, 64, 1, 32, 32, 0, true>;
    auto* kConv2 = gemm_k<128, 128, 32, 64, 4, 32, 0, 0, true>;
    auto* kGi    = gemm_k<128, 128, 32, 64, 4, 0, 0, 0, false>;
    auto* kGru   = gemm_k<32, 384, 16, 96, 4, 0, 0, 2, false>;
    auto* kHand  = gemm_k<128, 128, 32, 64, 4, 0, 0, 1, false>;
    auto* kFc1   = gemm_k<128, 128, 32, 64, 4, 0, 0, 0, true>;

    cudaFuncSetAttribute(kConv1, cudaFuncAttributeMaxDynamicSharedMemorySize, SM_STD);
    cudaFuncSetAttribute(kConv2, cudaFuncAttributeMaxDynamicSharedMemorySize, SM_STD);
    cudaFuncSetAttribute(kGi, cudaFuncAttributeMaxDynamicSharedMemorySize, SM_STD);
    cudaFuncSetAttribute(kGru, cudaFuncAttributeMaxDynamicSharedMemorySize, SM_GRU);
    cudaFuncSetAttribute(kHand, cudaFuncAttributeMaxDynamicSharedMemorySize, SM_STD);
    cudaFuncSetAttribute(kFc1, cudaFuncAttributeMaxDynamicSharedMemorySize, SM_STD);

    prep1<<<4096, 256>>>(poses, c1w, c2w, wih, whh, bih, bhh);
    foldw<<<1025, 128>>>(img_w, img_b, hand_w, hand_b);

    // conv1: im2col rows are contiguous slices of padded g_P (stride 51 -> VEC=1)
    kConv1<<<dim3(1024, 1), 256, SM_STD>>>(pP, 34 * 51, 51, 0, pW1, 128, c1b,
                                           pX1, 34 * 128, 128, 128, 160, nullptr, nullptr, 0);
    // conv2: contiguous im2col over time-padded X1
    kConv2<<<dim3(1024, 1), 256, SM_STD>>>(pX1, 34 * 128, 128, 0, pW2, 128, c2b,
                                           pX2, 0, 128, 0, 384, nullptr, nullptr, 0);
    // GRU input gates, biases folded
    kGi<<<dim3(1024, 3), 256, SM_STD>>>(pX2, 0, 128, 0, pWih, 384, pbgi,
                                        pGI, 0, 384, 0, 128, nullptr, nullptr, 0);
    // GRU recurrence: 32 in-place steps
    for (int t = 0; t < 32; t++)
        kGru<<<dim3(128, 1), 256, SM_GRU>>>(pH, 0, 128, 0, pWhh, 384, nullptr,
                                            pH, 0, 128, 0, 128, pGI, bhh + 256, t);
    // hand path with fused max epilogue
    kHand<<<dim3(2048, 1), 256, SM_STD>>>(hands, 0, 1024, 0, pWhand, 128, pbhand,
                                          pTrack, 0, 0, 0, 1024, nullptr, nullptr, 0);
    copyH<<<2048, 256>>>();
    // fc1
    kFc1<<<dim3(32, 2), 256, SM_STD>>>(pTrack, 0, 256, 0, fc1w, 256, fc1b,
                                       pH1, 0, 256, 0, 256, nullptr, nullptr, 0);
    // fc2 + segmented max + sigmoid
    fc2seg<<<16, 256>>>(fc2w, fc2b, vidx);
    finalk<<<2, 256>>>(nts, out);
}

// round 5
// speedup vs baseline: 2.1366x; 1.5196x over previous
#include <cuda_runtime.h>
#include <math.h>

#define NTRK 4096
#define NVID 512

// ------------------------- device scratch (no runtime allocation) -------------------------
__device__ float    g_P[NTRK * 34 * 51 + 64];   // time-padded poses (n, 34, 51)
__device__ float    g_W1[160 * 128];            // conv1 weights [k*51+ci (pad->160)][co]
__device__ float    g_W2[384 * 128];            // conv2 weights [k*128+ci][co]
__device__ float    g_Wih[128 * 384];           // gru_wih^T [k][3H]
__device__ float    g_Whh[128 * 384];           // gru_whh^T [k][3H]
__device__ float    g_bgi[384];                 // bih + bhh(r,z only)
__device__ float    g_Whand[1024 * 128];        // folded img_w @ hand_w
__device__ float    g_bhand[128];               // folded img_b @ hand_w + hand_b
__device__ float    g_X1[NTRK * 34 * 128];      // conv1 out, time-padded
__device__ float    g_X2[NTRK * 32 * 128];      // conv2 out
__device__ float    g_GI[NTRK * 32 * 384];      // precomputed GRU input gates
__device__ float    g_track[NTRK * 256];        // [kp_feat | hand_feat]
__device__ float    g_H1[NTRK * 256];           // fc1 out
__device__ unsigned g_vmax[NVID];               // ordered-encoded segment max

// ------------------------- helpers -------------------------
__device__ __forceinline__ float tf32r(float x) { asm("cvt.rna.tf32.f32 %0, %0;" : "+f"(x)); return x; }
__device__ __forceinline__ unsigned f2ord(float f) {
    unsigned u = __float_as_uint(f);
    return (u & 0x80000000u) ? ~u : (u | 0x80000000u);
}
__device__ __forceinline__ float ord2f(unsigned u) {
    return __uint_as_float((u & 0x80000000u) ? (u & 0x7fffffffu) : ~u);
}
__device__ __forceinline__ unsigned su32(const void* p) {
    unsigned r;
    asm("{.reg .u64 t; cvta.to.shared.u64 t, %1; cvt.u32.u64 %0, t;}" : "=r"(r) : "l"(p));
    return r;
}
__device__ __forceinline__ void cpa16(unsigned d, const void* s) {
    asm volatile("cp.async.cg.shared.global [%0],[%1],16;" :: "r"(d), "l"(s));
}
__device__ __forceinline__ void cpa4(unsigned d, const void* s) {
    asm volatile("cp.async.ca.shared.global [%0],[%1],4;" :: "r"(d), "l"(s));
}
__device__ __forceinline__ void cpcommit() { asm volatile("cp.async.commit_group;"); }
__device__ __forceinline__ void cpwait0() { asm volatile("cp.async.wait_group 0;"); }
__device__ __forceinline__ void cpwait1() { asm volatile("cp.async.wait_group 1;"); }
__device__ __forceinline__ void mma8(float* d, const unsigned* a, const unsigned* b) {
    asm volatile(
        "mma.sync.aligned.m16n8k8.row.col.f32.tf32.tf32.f32 "
        "{%0,%1,%2,%3},{%4,%5,%6,%7},{%8,%9},{%0,%1,%2,%3};"
        : "+f"(d[0]), "+f"(d[1]), "+f"(d[2]), "+f"(d[3])
        : "r"(a[0]), "r"(a[1]), "r"(a[2]), "r"(a[3]), "r"(b[0]), "r"(b[1]));
}
__device__ __forceinline__ float sigm(float x) { return 1.f / (1.f + __expf(-x)); }

// ------------------------- prep: layout/pad inputs, rearrange weights -------------------------
__global__ void prep1(const float* __restrict__ poses,
                      const float* __restrict__ c1w, const float* __restrict__ c2w,
                      const float* __restrict__ wih, const float* __restrict__ whh,
                      const float* __restrict__ bih, const float* __restrict__ bhh) {
    const long NP = (long)NTRK * 34 * 51;
    const long NX = (long)NTRK * 2 * 128;
    const long total = NP + NX + 20480 + 49152 + 49152 + 49152 + 384 + NVID;
    for (long i = (long)blockIdx.x * blockDim.x + threadIdx.x; i < total;
         i += (long)gridDim.x * blockDim.x) {
        long idx = i;
        if (idx < NP) {  // padded poses (n, 34, 51); rows tp=0,33 zero
            long n = idx / (34 * 51);
            int r = (int)(idx % (34 * 51));
            int tp = r / 51, ci = r % 51;
            g_P[idx] = (tp == 0 || tp == 33) ? 0.f : poses[(n * 32 + (tp - 1)) * 51 + ci];
            continue;
        }
        idx -= NP;
        if (idx < NX) {  // zero X1 pad rows tp=0,33
            long n = idx >> 8;
            int r = (int)(idx & 255);
            int tp = (r < 128) ? 0 : 33;
            g_X1[n * 34 * 128 + tp * 128 + (r & 127)] = 0.f;
            continue;
        }
        idx -= NX;
        if (idx < 20480) {  // W1 [kk][co], kk = ktap*51+ci, pad 153..159 zero
            int kk = (int)(idx >> 7), co = (int)(idx & 127);
            float v = 0.f;
            if (kk < 153) { int kt = kk / 51, ci = kk % 51; v = tf32r(c1w[co * 153 + ci * 3 + kt]); }
            g_W1[idx] = v;
            continue;
        }
        idx -= 20480;
        if (idx < 49152) {  // W2 [kk][co], kk = ktap*128+ci
            int kk = (int)(idx >> 7), co = (int)(idx & 127);
            int kt = kk >> 7, ci = kk & 127;
            g_W2[idx] = tf32r(c2w[co * 384 + ci * 3 + kt]);
            continue;
        }
        idx -= 49152;
        if (idx < 49152) {  // Wih^T [k][j]
            int k = (int)(idx / 384), j = (int)(idx % 384);
            g_Wih[idx] = tf32r(wih[j * 128 + k]);
            continue;
        }
        idx -= 49152;
        if (idx < 49152) {  // Whh^T [k][j]
            int k = (int)(idx / 384), j = (int)(idx % 384);
            g_Whh[idx] = tf32r(whh[j * 128 + k]);
            continue;
        }
        idx -= 49152;
        if (idx < 384) { g_bgi[idx] = bih[idx] + ((idx < 256) ? bhh[idx] : 0.f); continue; }
        idx -= 384;
        g_vmax[idx] = 0u;  // ord(-inf) < ord(any finite)
    }
}

// ------------------------- fold img_w @ hand_w (tiled fp32) -------------------------
// blocks 0..15: 64 rows x 128 cols each; block 16: bias row
__global__ void __launch_bounds__(256) foldw(const float* __restrict__ img_w,
                                             const float* __restrict__ img_b,
                                             const float* __restrict__ hand_w,
                                             const float* __restrict__ hand_b) {
    __shared__ float simg[64][68];
    __shared__ float shw[64][132];
    __shared__ float sv[512];
    int b = blockIdx.x, tid = threadIdx.x;
    if (b < 16) {
        int tr = tid >> 4;            // 0..15 -> rows tr*4..tr*4+3
        int tc = (tid & 15) * 8;      // col group
        float acc[4][8];
#pragma unroll
        for (int i = 0; i < 4; i++)
#pragma unroll
            for (int j = 0; j < 8; j++) acc[i][j] = 0.f;
        for (int kt = 0; kt < 512; kt += 64) {
            __syncthreads();
            // img tile 64x64: 4 float4 per thread
#pragma unroll
            for (int i = 0; i < 4; i++) {
                int ch = tid + i * 256;
                int r = ch >> 4, c4 = (ch & 15) * 4;
                *(float4*)&simg[r][c4] = *(const float4*)&img_w[(long)(b * 64 + r) * 512 + kt + c4];
            }
            // hand_w tile 64x128: 8 float4 per thread
#pragma unroll
            for (int i = 0; i < 8; i++) {
                int ch = tid + i * 256;
                int r = ch >> 5, c4 = (ch & 31) * 4;
                *(float4*)&shw[r][c4] = *(const float4*)&hand_w[(long)(kt + r) * 128 + c4];
            }
            __syncthreads();
#pragma unroll 8
            for (int q = 0; q < 64; q++) {
                float4 w0 = *(float4*)&shw[q][tc];
                float4 w1 = *(float4*)&shw[q][tc + 4];
#pragma unroll
                for (int i = 0; i < 4; i++) {
                    float a = simg[tr * 4 + i][q];
                    acc[i][0] += a * w0.x; acc[i][1] += a * w0.y;
                    acc[i][2] += a * w0.z; acc[i][3] += a * w0.w;
                    acc[i][4] += a * w1.x; acc[i][5] += a * w1.y;
                    acc[i][6] += a * w1.z; acc[i][7] += a * w1.w;
                }
            }
        }
#pragma unroll
        for (int i = 0; i < 4; i++)
#pragma unroll
            for (int j = 0; j < 8; j++)
                g_Whand[(long)(b * 64 + tr * 4 + i) * 128 + tc + j] = tf32r(acc[i][j]);
    } else {
        for (int q = tid; q < 512; q += 256) sv[q] = img_b[q];
        __syncthreads();
        if (tid < 128) {
            float a = hand_b[tid];
#pragma unroll 8
            for (int q = 0; q < 512; q++) a += sv[q] * hand_w[q * 128 + tid];
            g_bhand[tid] = a;
        }
    }
}

// ------------------------- generic tf32 GEMM -------------------------
// MODE 0: C = [relu](A@B + bias), group-addressed rows in/out
// MODE 1: hand GEMM, epilogue = per-track max over 64 rows -> g_track[:,128:]
template <int BM, int BN, int WM, int WN, int VEC, int ARPG, int ORPG, int MODE, bool RELU>
__global__ void __launch_bounds__(256) gemm_k(
    const float* __restrict__ A, long aGS, long aRS, long aOfs,
    const float* __restrict__ Bm, int ldb,
    const float* __restrict__ bias,
    float* __restrict__ Cout, long oGS, long oRS, long oOfs,
    int K) {
    constexpr int BK = 32;
    constexpr int WARPS_M = BM / WM, WARPS_N = BN / WN;
    static_assert(WARPS_M * WARPS_N == 8, "8 warps");
    constexpr int FM = WM / 16, FN = WN / 8;
    constexpr int SAST = BK + 4;   // 36 floats: conflict-free, 16B-aligned rows
    constexpr int SBST = BN + 8;   // conflict-free, 16B-aligned rows
    constexpr int ASZ = BM * SAST, BSZ = BK * SBST;
    extern __shared__ float sm[];
    float* sA = sm;
    float* sB = sm + 2 * ASZ;

    const int tid = threadIdx.x, lane = tid & 31, wid = tid >> 5;
    const int wm = wid % WARPS_M, wn = wid / WARPS_M;
    const int m0 = blockIdx.x * BM, n0 = blockIdx.y * BN;

    float acc[FM][FN][4];
#pragma unroll
    for (int i = 0; i < FM; i++)
#pragma unroll
        for (int j = 0; j < FN; j++)
#pragma unroll
            for (int q = 0; q < 4; q++) acc[i][j][q] = 0.f;

    constexpr int A_LOADS = BM * BK / (256 * VEC);
    const float* aP[A_LOADS];
    unsigned aD[A_LOADS];
#pragma unroll
    for (int i = 0; i < A_LOADS; i++) {
        int ch = tid + i * 256;
        int row, cx;
        if (VEC == 4) { row = ch >> 3; cx = (ch & 7) * 4; }
        else          { row = ch >> 5; cx = ch & 31; }
        int gr = m0 + row;
        const float* rp = ARPG ? (A + (long)(gr / ARPG) * aGS + (long)(gr % ARPG) * aRS + aOfs)
                               : (A + (long)gr * aRS + aOfs);
        aP[i] = rp + cx;
        aD[i] = su32(sA) + (unsigned)((row * SAST + cx) * 4);
    }
    constexpr int B_LOADS = BK * BN / 1024;
    const float* bP[B_LOADS];
    unsigned bD[B_LOADS];
#pragma unroll
    for (int i = 0; i < B_LOADS; i++) {
        int ch = tid + i * 256;
        int row = ch / (BN / 4);
        int cx = (ch % (BN / 4)) * 4;
        bP[i] = Bm + (long)row * ldb + n0 + cx;
        bD[i] = su32(sB) + (unsigned)((row * SBST + cx) * 4);
    }

    auto load = [&](int buf, int k0) {
#pragma unroll
        for (int i = 0; i < A_LOADS; i++) {
            if (VEC == 4) cpa16(aD[i] + buf * ASZ * 4, aP[i] + k0);
            else          cpa4(aD[i] + buf * ASZ * 4, aP[i] + k0);
        }
#pragma unroll
        for (int i = 0; i < B_LOADS; i++) cpa16(bD[i] + buf * BSZ * 4, bP[i] + (long)k0 * ldb);
        cpcommit();
    };

    const int NS = K / BK;
    load(0, 0);
    for (int s = 0; s < NS; s++) {
        if (s + 1 < NS) { load((s + 1) & 1, (s + 1) * BK); cpwait1(); }
        else cpwait0();
        __syncthreads();
        const float* cA = sA + (s & 1) * ASZ;
        const float* cB = sB + (s & 1) * BSZ;
#pragma unroll
        for (int kk = 0; kk < BK; kk += 8) {
            unsigned af[FM][4], bf[FN][2];
            const int ar0 = wm * WM + (lane >> 2), ac = kk + (lane & 3);
#pragma unroll
            for (int i = 0; i < FM; i++) {
                int r = ar0 + i * 16;
                af[i][0] = __float_as_uint(cA[(r) * SAST + ac]);
                af[i][1] = __float_as_uint(cA[(r + 8) * SAST + ac]);
                af[i][2] = __float_as_uint(cA[(r) * SAST + ac + 4]);
                af[i][3] = __float_as_uint(cA[(r + 8) * SAST + ac + 4]);
            }
            const int bc0 = wn * WN + (lane >> 2), br = kk + (lane & 3);
#pragma unroll
            for (int j = 0; j < FN; j++) {
                bf[j][0] = __float_as_uint(cB[(br) * SBST + bc0 + j * 8]);
                bf[j][1] = __float_as_uint(cB[(br + 4) * SBST + bc0 + j * 8]);
            }
#pragma unroll
            for (int i = 0; i < FM; i++)
#pragma unroll
                for (int j = 0; j < FN; j++) mma8(acc[i][j], af[i], bf[j]);
        }
        __syncthreads();
    }

    // ------------------------- epilogue -------------------------
    if (MODE == 0) {
#pragma unroll
        for (int i = 0; i < FM; i++) {
            int lr = wm * WM + i * 16 + (lane >> 2);
#pragma unroll
            for (int j = 0; j < FN; j++) {
                int col = n0 + wn * WN + j * 8 + (lane & 3) * 2;
                float b0 = bias ? bias[col] : 0.f;
                float b1 = bias ? bias[col + 1] : 0.f;
#pragma unroll
                for (int h = 0; h < 2; h++) {
                    int gr = m0 + lr + h * 8;
                    float v0 = acc[i][j][h * 2 + 0] + b0;
                    float v1 = acc[i][j][h * 2 + 1] + b1;
                    if (RELU) { v0 = fmaxf(v0, 0.f); v1 = fmaxf(v1, 0.f); }
                    float* op = ORPG ? (Cout + (long)(gr / ORPG) * oGS + (long)(gr % ORPG) * oRS + oOfs + col)
                                     : (Cout + (long)gr * oRS + oOfs + col);
                    ((float2*)op)[0] = make_float2(v0, v1);
                }
            }
        }
    } else {  // MODE 1: hand, per-track max over 64 rows (2 tracks / block)
        __syncthreads();
        constexpr int CST = 132;
#pragma unroll
        for (int i = 0; i < FM; i++) {
            int lr = wm * WM + i * 16 + (lane >> 2);
#pragma unroll
            for (int j = 0; j < FN; j++) {
                int lc = wn * WN + j * 8 + (lane & 3) * 2;
                ((float2*)&sm[(lr) * CST + lc])[0] = make_float2(acc[i][j][0], acc[i][j][1]);
                ((float2*)&sm[(lr + 8) * CST + lc])[0] = make_float2(acc[i][j][2], acc[i][j][3]);
            }
        }
        __syncthreads();
        int trk = tid >> 7, c = tid & 127;
        float mx = -3.4e38f;
#pragma unroll 8
        for (int r = 0; r < 64; r++) mx = fmaxf(mx, sm[(trk * 64 + r) * CST + c]);
        mx += bias[c];
        int track = (m0 >> 6) + trk;
        Cout[(long)track * 256 + 128 + c] = mx;
    }
}

// ------------------------- fused GRU: Whh resident in smem, 32 steps, 1 launch ---------------
// 128 blocks x 256 thr; block owns 32 tracks. Warp w owns gate cols {w*16..w*16+15} of r,z,n.
__global__ void __launch_bounds__(256) gru_fused(
    const float* __restrict__ whhT,   // [k=128][j=384] (g_Whh)
    const float* __restrict__ gi,     // [trk][t][384]
    const float* __restrict__ bhhn,   // bhh + 256
    float* __restrict__ trackOut) {
    extern __shared__ float sm[];
    float* sW = sm;                    // [128][388]
    float* sh = sm + 128 * 388;        // [32][132]
    const int tid = threadIdx.x, lane = tid & 31, w = tid >> 5;
    const int m0 = blockIdx.x * 32;
    const int rb = lane >> 2, cq = lane & 3, cb = cq * 2;

    // load Whh into smem once (12288 float4)
    {
        unsigned base = su32(sW);
#pragma unroll
        for (int i = 0; i < 48; i++) {
            int ch = tid + i * 256;
            int row = ch / 96, cx = (ch % 96) * 4;
            cpa16(base + (unsigned)((row * 388 + cx) * 4), whhT + row * 384 + cx);
        }
        cpcommit();
    }
    for (int i = tid; i < 32 * 132; i += 256) sh[i] = 0.f;
    cpwait0();
    __syncthreads();

    float bn[2][2];
#pragma unroll
    for (int jj = 0; jj < 2; jj++) {
        int c = w * 16 + jj * 8 + cb;
        bn[jj][0] = bhhn[c];
        bn[jj][1] = bhhn[c + 1];
    }

    for (int step = 0; step < 32; step++) {
        float acc[6][2][4];
#pragma unroll
        for (int f = 0; f < 6; f++)
#pragma unroll
            for (int i = 0; i < 2; i++)
#pragma unroll
                for (int q = 0; q < 4; q++) acc[f][i][q] = 0.f;

#pragma unroll
        for (int kk = 0; kk < 128; kk += 8) {
            unsigned af[2][4];
#pragma unroll
            for (int i = 0; i < 2; i++) {
                int r = i * 16 + rb, ac = kk + cq;
                af[i][0] = __float_as_uint(sh[r * 132 + ac]);
                af[i][1] = __float_as_uint(sh[(r + 8) * 132 + ac]);
                af[i][2] = __float_as_uint(sh[r * 132 + ac + 4]);
                af[i][3] = __float_as_uint(sh[(r + 8) * 132 + ac + 4]);
            }
#pragma unroll
            for (int g = 0; g < 3; g++)
#pragma unroll
                for (int jj = 0; jj < 2; jj++) {
                    int col = g * 128 + w * 16 + jj * 8 + rb;
                    unsigned bf[2];
                    bf[0] = __float_as_uint(sW[(kk + cq) * 388 + col]);
                    bf[1] = __float_as_uint(sW[(kk + 4 + cq) * 388 + col]);
                    mma8(acc[g * 2 + jj][0], af[0], bf);
                    mma8(acc[g * 2 + jj][1], af[1], bf);
                }
        }
        __syncthreads();  // all mma reads of h done before anyone rewrites h

#pragma unroll
        for (int i = 0; i < 2; i++)
#pragma unroll
            for (int rh = 0; rh < 2; rh++) {
                int row = rb + i * 16 + rh * 8;
                const float* gp = gi + ((long)(m0 + row) * 32 + step) * 384;
                int q = rh * 2;
#pragma unroll
                for (int jj = 0; jj < 2; jj++) {
                    int c = w * 16 + jj * 8 + cb;
                    float2 gir = *(const float2*)(gp + c);
                    float2 giz = *(const float2*)(gp + 128 + c);
                    float2 gin = *(const float2*)(gp + 256 + c);
                    float2 hold = *(const float2*)(sh + row * 132 + c);
                    float r0 = sigm(gir.x + acc[jj][i][q]);
                    float r1 = sigm(gir.y + acc[jj][i][q + 1]);
                    float z0 = sigm(giz.x + acc[2 + jj][i][q]);
                    float z1 = sigm(giz.y + acc[2 + jj][i][q + 1]);
                    float n0 = tanhf(gin.x + r0 * (acc[4 + jj][i][q] + bn[jj][0]));
                    float n1 = tanhf(gin.y + r1 * (acc[4 + jj][i][q + 1] + bn[jj][1]));
                    float2 hnew;
                    hnew.x = (1.f - z0) * n0 + z0 * hold.x;
                    hnew.y = (1.f - z1) * n1 + z1 * hold.y;
                    *(float2*)(sh + row * 132 + c) = hnew;
                }
            }
        __syncthreads();  // h fully updated before next step's mma
    }

    // write h -> track[:, 0:128]
#pragma unroll
    for (int it = 0; it < 16; it++) {
        int idx = it * 256 + tid;
        int row = idx >> 7, c = idx & 127;
        trackOut[(long)(m0 + row) * 256 + c] = sh[row * 132 + c];
    }
}

// ------------------------- small kernels -------------------------
__global__ void fc2seg(const float* __restrict__ w, const float* __restrict__ b2,
                       const int* __restrict__ vidx) {
    __shared__ float sw[256];
    int t = threadIdx.x;
    sw[t] = w[t];
    __syncthreads();
    int m = blockIdx.x * 256 + t;
    const float* h = &g_H1[(long)m * 256];
    float a = b2[0];
#pragma unroll 16
    for (int q = 0; q < 256; q++) a += h[q] * sw[q];
    atomicMax(&g_vmax[vidx[m]], f2ord(a));
}

__global__ void finalk(const float* __restrict__ nts, float* __restrict__ out) {
    int v = blockIdx.x * 256 + threadIdx.x;
    if (v < NVID) {
        unsigned u = g_vmax[v];
        float lg = (u == 0u) ? nts[0] : ord2f(u);
        out[v] = 1.f / (1.f + expf(-lg));
    }
}

// ------------------------- launch -------------------------
extern "C" void kernel_launch(void* const* d_in, const int* in_sizes, int n_in,
                              void* d_out, int out_size) {
    const float* poses  = (const float*)d_in[0];
    const float* hands  = (const float*)d_in[1];
    const int*   vidx   = (const int*)d_in[2];
    const float* c1w    = (const float*)d_in[3];
    const float* c1b    = (const float*)d_in[4];
    const float* c2w    = (const float*)d_in[5];
    const float* c2b    = (const float*)d_in[6];
    const float* wih    = (const float*)d_in[7];
    const float* whh    = (const float*)d_in[8];
    const float* bih    = (const float*)d_in[9];
    const float* bhh    = (const float*)d_in[10];
    const float* img_w  = (const float*)d_in[11];
    const float* img_b  = (const float*)d_in[12];
    const float* hand_w = (const float*)d_in[13];
    const float* hand_b = (const float*)d_in[14];
    const float* fc1w   = (const float*)d_in[15];
    const float* fc1b   = (const float*)d_in[16];
    const float* fc2w   = (const float*)d_in[17];
    const float* fc2b   = (const float*)d_in[18];
    const float* nts    = (const float*)d_in[19];
    float* out = (float*)d_out;

    float *pP, *pW1, *pW2, *pWih, *pWhh, *pbgi, *pWhand, *pbhand, *pX1, *pX2, *pGI, *pTrack, *pH1;
    cudaGetSymbolAddress((void**)&pP, g_P);
    cudaGetSymbolAddress((void**)&pW1, g_W1);
    cudaGetSymbolAddress((void**)&pW2, g_W2);
    cudaGetSymbolAddress((void**)&pWih, g_Wih);
    cudaGetSymbolAddress((void**)&pWhh, g_Whh);
    cudaGetSymbolAddress((void**)&pbgi, g_bgi);
    cudaGetSymbolAddress((void**)&pWhand, g_Whand);
    cudaGetSymbolAddress((void**)&pbhand, g_bhand);
    cudaGetSymbolAddress((void**)&pX1, g_X1);
    cudaGetSymbolAddress((void**)&pX2, g_X2);
    cudaGetSymbolAddress((void**)&pGI, g_GI);
    cudaGetSymbolAddress((void**)&pTrack, g_track);
    cudaGetSymbolAddress((void**)&pH1, g_H1);

    constexpr int SM_STD = (2 * 128 * 36 + 2 * 32 * 136) * 4;        // 71680 B
    constexpr int SM_GRUF = (128 * 388 + 32 * 132) * 4;              // 215552 B

    auto* kConv1 = gemm_k<128, 128, 32, 64, 1, 32, 32, 0, true>;
    auto* kConv2 = gemm_k<128, 128, 32, 64, 4, 32, 0, 0, true>;
    auto* kGi    = gemm_k<128, 128, 32, 64, 4, 0, 0, 0, false>;
    auto* kHand  = gemm_k<128, 128, 32, 64, 4, 0, 0, 1, false>;
    auto* kFc1   = gemm_k<128, 128, 32, 64, 4, 0, 0, 0, true>;

    cudaFuncSetAttribute(kConv1, cudaFuncAttributeMaxDynamicSharedMemorySize, SM_STD);
    cudaFuncSetAttribute(kConv2, cudaFuncAttributeMaxDynamicSharedMemorySize, SM_STD);
    cudaFuncSetAttribute(kGi, cudaFuncAttributeMaxDynamicSharedMemorySize, SM_STD);
    cudaFuncSetAttribute(kHand, cudaFuncAttributeMaxDynamicSharedMemorySize, SM_STD);
    cudaFuncSetAttribute(kFc1, cudaFuncAttributeMaxDynamicSharedMemorySize, SM_STD);
    cudaFuncSetAttribute(gru_fused, cudaFuncAttributeMaxDynamicSharedMemorySize, SM_GRUF);

    prep1<<<4096, 256>>>(poses, c1w, c2w, wih, whh, bih, bhh);
    foldw<<<17, 256>>>(img_w, img_b, hand_w, hand_b);

    // conv1: im2col rows are contiguous slices of padded g_P (stride 51 -> VEC=1)
    kConv1<<<dim3(1024, 1), 256, SM_STD>>>(pP, 34 * 51, 51, 0, pW1, 128, c1b,
                                           pX1, 34 * 128, 128, 128, 160);
    // conv2: contiguous im2col over time-padded X1
    kConv2<<<dim3(1024, 1), 256, SM_STD>>>(pX1, 34 * 128, 128, 0, pW2, 128, c2b,
                                           pX2, 0, 128, 0, 384);
    // GRU input gates, biases folded
    kGi<<<dim3(1024, 3), 256, SM_STD>>>(pX2, 0, 128, 0, pWih, 384, pbgi,
                                        pGI, 0, 384, 0, 128);
    // GRU recurrence: single fused launch, writes kp_feat into g_track[:,0:128]
    gru_fused<<<128, 256, SM_GRUF>>>(pWhh, pGI, bhh + 256, pTrack);
    // hand path with fused max epilogue -> g_track[:,128:]
    kHand<<<dim3(2048, 1), 256, SM_STD>>>(hands, 0, 1024, 0, pWhand, 128, pbhand,
                                          pTrack, 0, 0, 0, 1024);
    // fc1
    kFc1<<<dim3(32, 2), 256, SM_STD>>>(pTrack, 0, 256, 0, fc1w, 256, fc1b,
                                       pH1, 0, 256, 0, 256);
    // fc2 + segmented max + sigmoid
    fc2seg<<<16, 256>>>(fc2w, fc2b, vidx);
    finalk<<<2, 256>>>(nts, out);
}